// round 13
// baseline (speedup 1.0000x reference)
#include <cuda_runtime.h>
#include <cuda_fp16.h>
#include <cstdint>

// Problem constants (fixed by the reference setup_inputs)
#define BB 8
#define NN 200000
#define CC 32
#define RR 128
#define R2 (RR * RR)          // 16384 bins per plane
#define NPLANES 3

// Scratch: fp16 channel-contiguous accumulators + per-bin int counts.
// acc layout: [b][plane][bin][c] as half2 pairs -> 64B per bin, 16B-aligned v4 targets.
// Zero-initialized at module load (BSS); finalize_kernel re-zeroes after reading,
// so every kernel_launch call (first correctness run + every graph replay) sees
// clean scratch. 128B alignment for uint4 zero-stores.
__device__ __align__(128) __half2 g_acc[(size_t)BB * NPLANES * R2 * (CC / 2)];  // ~25.2 MB
__device__ __align__(128) int     g_cnt[(size_t)BB * NPLANES * R2];             // ~1.5 MB

// ---------------------------------------------------------------------------
// Bit-exact replication of the reference binning:
//   xyz_norm = (x + 1)/2 - 0.5
//   u = xyz_norm / 1.00001f + 0.5 ; clamp [0, 0.99999f] ; idx = (int)(u*128)
// /2 done as *0.5 (exact, power of two); /1.00001f stays IEEE div (must not
// become reciprocal-mul: ~40 of 1.6M points would flip bins). No FMA contraction.
// ---------------------------------------------------------------------------
__device__ __forceinline__ int bin_of(float x) {
    float v = __fsub_rn(__fmul_rn(__fadd_rn(x, 1.0f), 0.5f), 0.5f);
    v = __fadd_rn(__fdiv_rn(v, 1.00001f), 0.5f);
    v = fminf(fmaxf(v, 0.0f), 0.99999f);
    return (int)__fmul_rn(v, 128.0f);
}

// Pack two fp32 into f16x2 bits: lo = a (channel c), hi = b (channel c+1)
__device__ __forceinline__ unsigned pack_h2(float a, float b) {
    unsigned u;
    asm("cvt.rn.f16x2.f32 %0, %1, %2;" : "=r"(u) : "f"(b), "f"(a));
    return u;
}

__device__ __forceinline__ void red_add_v4h2(__half2* addr, unsigned u0, unsigned u1,
                                             unsigned u2, unsigned u3) {
    asm volatile("red.global.add.noftz.v4.f16x2 [%0], {%1, %2, %3, %4};"
                 :: "l"(addr), "r"(u0), "r"(u1), "r"(u2), "r"(u3)
                 : "memory");
}

// ---------------------------------------------------------------------------
// Kernel 1: scatter (frozen champion shape). One thread per 4 consecutive
// points. Per point: 12 red.v4.f16x2 + 3 u32 count REDGs = 15 lane messages
// (structural LSU floor for exact counts), ~1.4 load sectors.
// ---------------------------------------------------------------------------
__global__ void scatter_kernel(const float* __restrict__ xyz,
                               const float* __restrict__ feat) {
    const int NQ = NN / 4;                      // 50000 point-quads per batch
    int t = blockIdx.x * blockDim.x + threadIdx.x;
    if (t >= BB * NQ) return;
    int b  = t / NQ;
    int n0 = (t - b * NQ) * 4;

    // 4 points = 12 floats = 3 float4 (16B-aligned: n0 % 4 == 0)
    const float4* p4 = reinterpret_cast<const float4*>(xyz + ((size_t)b * NN + n0) * 3);
    float4 q0 = __ldg(p4 + 0);
    float4 q1 = __ldg(p4 + 1);
    float4 q2 = __ldg(p4 + 2);

    float px[4] = {q0.x, q0.w, q1.z, q2.y};
    float py[4] = {q0.y, q1.x, q1.w, q2.z};
    float pz[4] = {q0.z, q1.y, q2.x, q2.w};

    int l_xy[4], l_yz[4], l_xz[4];
    const size_t base = (size_t)b * NPLANES * R2;
#pragma unroll
    for (int j = 0; j < 4; j++) {
        int bx = bin_of(px[j]), by = bin_of(py[j]), bz = bin_of(pz[j]);
        l_xy[j] = bx + RR * by;    // plane "xy": dims (0,1)
        l_yz[j] = by + RR * bz;    // plane "yz": dims (1,2)
        l_xz[j] = bx + RR * bz;    // plane "xz": dims (0,2)
        atomicAdd(&g_cnt[base + 0 * R2 + l_xy[j]], 1);
        atomicAdd(&g_cnt[base + 1 * R2 + l_yz[j]], 1);
        atomicAdd(&g_cnt[base + 2 * R2 + l_xz[j]], 1);
    }

    __half2* a0[4];
    __half2* a1[4];
    __half2* a2[4];
#pragma unroll
    for (int j = 0; j < 4; j++) {
        a0[j] = g_acc + (base + 0 * R2 + l_xy[j]) * (CC / 2);
        a1[j] = g_acc + (base + 1 * R2 + l_yz[j]) * (CC / 2);
        a2[j] = g_acc + (base + 2 * R2 + l_xz[j]) * (CC / 2);
    }

    const float* fb = feat + (size_t)b * CC * NN + n0;
#pragma unroll
    for (int c = 0; c < CC; c += 8) {
        // v[k] = channel c+k values for points 0..3 (float4 over n)
        float4 v[8];
#pragma unroll
        for (int k = 0; k < 8; k++)
            v[k] = __ldg(reinterpret_cast<const float4*>(fb + (size_t)(c + k) * NN));

        const float* vf = reinterpret_cast<const float*>(v);   // vf[k*4 + j]
#pragma unroll
        for (int j = 0; j < 4; j++) {
            unsigned u0 = pack_h2(vf[0 * 4 + j], vf[1 * 4 + j]);
            unsigned u1 = pack_h2(vf[2 * 4 + j], vf[3 * 4 + j]);
            unsigned u2 = pack_h2(vf[4 * 4 + j], vf[5 * 4 + j]);
            unsigned u3 = pack_h2(vf[6 * 4 + j], vf[7 * 4 + j]);
            int cg = c / 2;   // half2 offset of this 8-channel group
            red_add_v4h2(a0[j] + cg, u0, u1, u2, u3);
            red_add_v4h2(a1[j] + cg, u0, u1, u2, u3);
            red_add_v4h2(a2[j] + cg, u0, u1, u2, u3);
        }
    }
}

// ---------------------------------------------------------------------------
// Kernel 2: finalize + self-clean. 128-bin tile per block:
//   - read fp16 accumulators (coalesced 4B loads) into smem, transpose
//   - per-bin reciprocal of count
//   - AFTER the barrier: zero this block's exclusive acc/cnt region with
//     coalesced uint4 stores (restores the pre-launch invariant for replays)
//   - write output float4 (fully coalesced 16B stores)
// blockDim 256; grid (R2/128, B*3).
// ---------------------------------------------------------------------------
__global__ void finalize_kernel(float* __restrict__ out) {
    __shared__ float tile[128][33];
    __shared__ float rcp[128];
    int bp   = blockIdx.y;              // 0 .. B*3-1
    int lin0 = blockIdx.x * 128;
    int tid  = threadIdx.x;             // 0..255

    // 128 bins x 16 half2 = 2048 half2; 8 per thread, coalesced 4B loads.
    const __half2* rp = g_acc + ((size_t)bp * R2 + lin0) * (CC / 2);
#pragma unroll
    for (int e = tid; e < 128 * (CC / 2); e += 256) {
        int bin  = e >> 4;
        int col2 = e & 15;
        float2 f = __half22float2(rp[e]);
        tile[bin][col2 * 2 + 0] = f.x;
        tile[bin][col2 * 2 + 1] = f.y;
    }
    if (tid < 128) {
        int c = g_cnt[(size_t)bp * R2 + lin0 + tid];
        rcp[tid] = __frcp_rn(fmaxf((float)c, 1.0f));
    }
    __syncthreads();

    // Self-clean: zero this block's acc region (2048 half2 = 512 uint4) and
    // cnt region (128 int = 32 uint4). Exclusive per block, 16B-aligned.
    {
        const uint4 z = make_uint4(0, 0, 0, 0);
        uint4* za = reinterpret_cast<uint4*>(
            g_acc + ((size_t)bp * R2 + lin0) * (CC / 2));
        za[tid]       = z;
        za[tid + 256] = z;
        if (tid < 32)
            reinterpret_cast<uint4*>(g_cnt + (size_t)bp * R2 + lin0)[tid] = z;
    }

    // thread t: channel c = t>>3, bin-quads (t&7) + 8k, k=0..3 -> float4 stores
    int c = tid >> 3;
    float* op = out + ((size_t)bp * CC + c) * R2 + lin0;
#pragma unroll
    for (int k = 0; k < 4; k++) {
        int qd = (tid & 7) + 8 * k;
        int b0 = qd * 4;
        float4 v;
        v.x = tile[b0 + 0][c] * rcp[b0 + 0];
        v.y = tile[b0 + 1][c] * rcp[b0 + 1];
        v.z = tile[b0 + 2][c] * rcp[b0 + 2];
        v.w = tile[b0 + 3][c] * rcp[b0 + 3];
        reinterpret_cast<float4*>(op)[qd] = v;
    }
}

// ---------------------------------------------------------------------------
extern "C" void kernel_launch(void* const* d_in, const int* in_sizes, int n_in,
                              void* d_out, int out_size) {
    const float* xyz  = (const float*)d_in[0];   // (B, N, 3) float32
    const float* feat = (const float*)d_in[1];   // (B, C, N) float32
    float* out = (float*)d_out;                  // (B, 3, C, R, R) float32

    // No zeroing kernel: scratch is zero at module load, and finalize_kernel
    // restores the all-zero state after every run (self-cleaning invariant).

    int nthreads = BB * (NN / 4);                // 400000
    scatter_kernel<<<(nthreads + 255) / 256, 256>>>(xyz, feat);

    dim3 fg(R2 / 128, BB * NPLANES);
    finalize_kernel<<<fg, 256>>>(out);
}

// round 15
// speedup vs baseline: 1.0134x; 1.0134x over previous
#include <cuda_runtime.h>
#include <cuda_fp16.h>
#include <cstdint>

// Problem constants (fixed by the reference setup_inputs)
#define BB 8
#define NN 200000
#define CC 32
#define RR 128
#define R2 (RR * RR)          // 16384 bins per plane
#define NPLANES 3

// Scratch: fp16 channel-contiguous accumulators + per-bin int counts.
// acc layout: [b][plane][bin][c] as half2 pairs -> 64B per bin, 16B-aligned v4 targets
__device__ __align__(128) __half2 g_acc[(size_t)BB * NPLANES * R2 * (CC / 2)];  // ~25.2 MB
__device__ __align__(128) int     g_cnt[(size_t)BB * NPLANES * R2];             // ~1.5 MB

// ---------------------------------------------------------------------------
// Bit-exact replication of the reference binning:
//   xyz_norm = (x + 1)/2 - 0.5
//   u = xyz_norm / 1.00001f + 0.5 ; clamp [0, 0.99999f] ; idx = (int)(u*128)
// /2 done as *0.5 (exact, power of two); /1.00001f stays IEEE div (must not
// become reciprocal-mul: ~40 of 1.6M points would flip bins). No FMA contraction.
// ---------------------------------------------------------------------------
__device__ __forceinline__ int bin_of(float x) {
    float v = __fsub_rn(__fmul_rn(__fadd_rn(x, 1.0f), 0.5f), 0.5f);
    v = __fadd_rn(__fdiv_rn(v, 1.00001f), 0.5f);
    v = fminf(fmaxf(v, 0.0f), 0.99999f);
    return (int)__fmul_rn(v, 128.0f);
}

// Pack two fp32 into f16x2 bits: lo = a (channel c), hi = b (channel c+1)
__device__ __forceinline__ unsigned pack_h2(float a, float b) {
    unsigned u;
    asm("cvt.rn.f16x2.f32 %0, %1, %2;" : "=r"(u) : "f"(b), "f"(a));
    return u;
}

__device__ __forceinline__ void red_add_v4h2(__half2* addr, unsigned u0, unsigned u1,
                                             unsigned u2, unsigned u3) {
    asm volatile("red.global.add.noftz.v4.f16x2 [%0], {%1, %2, %3, %4};"
                 :: "l"(addr), "r"(u0), "r"(u1), "r"(u2), "r"(u3)
                 : "memory");
}

// ---------------------------------------------------------------------------
// Kernel 1: scatter (frozen champion shape). One thread per 4 consecutive
// points. Per point: 12 red.v4.f16x2 + 3 u32 count REDGs = 15 lane messages
// (structural LSU floor for exact counts), ~1.4 load sectors.
// ---------------------------------------------------------------------------
__global__ void scatter_kernel(const float* __restrict__ xyz,
                               const float* __restrict__ feat) {
    const int NQ = NN / 4;                      // 50000 point-quads per batch
    int t = blockIdx.x * blockDim.x + threadIdx.x;
    if (t >= BB * NQ) return;
    int b  = t / NQ;
    int n0 = (t - b * NQ) * 4;

    // 4 points = 12 floats = 3 float4 (16B-aligned: n0 % 4 == 0)
    const float4* p4 = reinterpret_cast<const float4*>(xyz + ((size_t)b * NN + n0) * 3);
    float4 q0 = __ldg(p4 + 0);
    float4 q1 = __ldg(p4 + 1);
    float4 q2 = __ldg(p4 + 2);

    float px[4] = {q0.x, q0.w, q1.z, q2.y};
    float py[4] = {q0.y, q1.x, q1.w, q2.z};
    float pz[4] = {q0.z, q1.y, q2.x, q2.w};

    int l_xy[4], l_yz[4], l_xz[4];
    const size_t base = (size_t)b * NPLANES * R2;
#pragma unroll
    for (int j = 0; j < 4; j++) {
        int bx = bin_of(px[j]), by = bin_of(py[j]), bz = bin_of(pz[j]);
        l_xy[j] = bx + RR * by;    // plane "xy": dims (0,1)
        l_yz[j] = by + RR * bz;    // plane "yz": dims (1,2)
        l_xz[j] = bx + RR * bz;    // plane "xz": dims (0,2)
        atomicAdd(&g_cnt[base + 0 * R2 + l_xy[j]], 1);
        atomicAdd(&g_cnt[base + 1 * R2 + l_yz[j]], 1);
        atomicAdd(&g_cnt[base + 2 * R2 + l_xz[j]], 1);
    }

    __half2* a0[4];
    __half2* a1[4];
    __half2* a2[4];
#pragma unroll
    for (int j = 0; j < 4; j++) {
        a0[j] = g_acc + (base + 0 * R2 + l_xy[j]) * (CC / 2);
        a1[j] = g_acc + (base + 1 * R2 + l_yz[j]) * (CC / 2);
        a2[j] = g_acc + (base + 2 * R2 + l_xz[j]) * (CC / 2);
    }

    const float* fb = feat + (size_t)b * CC * NN + n0;
#pragma unroll
    for (int c = 0; c < CC; c += 8) {
        // v[k] = channel c+k values for points 0..3 (float4 over n)
        float4 v[8];
#pragma unroll
        for (int k = 0; k < 8; k++)
            v[k] = __ldg(reinterpret_cast<const float4*>(fb + (size_t)(c + k) * NN));

        const float* vf = reinterpret_cast<const float*>(v);   // vf[k*4 + j]
#pragma unroll
        for (int j = 0; j < 4; j++) {
            unsigned u0 = pack_h2(vf[0 * 4 + j], vf[1 * 4 + j]);
            unsigned u1 = pack_h2(vf[2 * 4 + j], vf[3 * 4 + j]);
            unsigned u2 = pack_h2(vf[4 * 4 + j], vf[5 * 4 + j]);
            unsigned u3 = pack_h2(vf[6 * 4 + j], vf[7 * 4 + j]);
            int cg = c / 2;   // half2 offset of this 8-channel group
            red_add_v4h2(a0[j] + cg, u0, u1, u2, u3);
            red_add_v4h2(a1[j] + cg, u0, u1, u2, u3);
            red_add_v4h2(a2[j] + cg, u0, u1, u2, u3);
        }
    }
}

// ---------------------------------------------------------------------------
// Kernel 2: finalize (R10 champion). 128-bin tile per block: read fp16
// accumulators (coalesced 4B loads), transpose [bin][c] -> [c][bin] via smem,
// multiply by per-bin reciprocal of count, write float4 (coalesced 16B stores).
// blockDim 256; grid (R2/128, B*3).
// ---------------------------------------------------------------------------
__global__ void finalize_kernel(float* __restrict__ out) {
    __shared__ float tile[128][33];
    __shared__ float rcp[128];
    int bp   = blockIdx.y;              // 0 .. B*3-1
    int lin0 = blockIdx.x * 128;
    int tid  = threadIdx.x;             // 0..255

    // 128 bins x 16 half2 = 2048 half2; 8 per thread, coalesced 4B loads.
    const __half2* rp = g_acc + ((size_t)bp * R2 + lin0) * (CC / 2);
#pragma unroll
    for (int e = tid; e < 128 * (CC / 2); e += 256) {
        int bin  = e >> 4;
        int col2 = e & 15;
        float2 f = __half22float2(rp[e]);
        tile[bin][col2 * 2 + 0] = f.x;
        tile[bin][col2 * 2 + 1] = f.y;
    }
    if (tid < 128) {
        int c = g_cnt[(size_t)bp * R2 + lin0 + tid];
        rcp[tid] = __frcp_rn(fmaxf((float)c, 1.0f));
    }
    __syncthreads();

    // thread t: channel c = t>>3, bin-quads (t&7) + 8k, k=0..3 -> float4 stores
    int c = tid >> 3;
    float* op = out + ((size_t)bp * CC + c) * R2 + lin0;
#pragma unroll
    for (int k = 0; k < 4; k++) {
        int qd = (tid & 7) + 8 * k;
        int b0 = qd * 4;
        float4 v;
        v.x = tile[b0 + 0][c] * rcp[b0 + 0];
        v.y = tile[b0 + 1][c] * rcp[b0 + 1];
        v.z = tile[b0 + 2][c] * rcp[b0 + 2];
        v.w = tile[b0 + 3][c] * rcp[b0 + 3];
        reinterpret_cast<float4*>(op)[qd] = v;
    }
}

// ---------------------------------------------------------------------------
// Fallback zero kernel (used only if symbol-address lookup ever fails).
// ---------------------------------------------------------------------------
__global__ void zero_scratch_kernel() {
    const size_t n_acc4 = (size_t)BB * NPLANES * R2 * (CC / 2) / 4;
    const size_t n_cnt4 = (size_t)BB * NPLANES * R2 / 4;
    float4* acc4 = reinterpret_cast<float4*>(g_acc);
    int4*   cnt4 = reinterpret_cast<int4*>(g_cnt);
    const float4 fz = make_float4(0.f, 0.f, 0.f, 0.f);
    const int4   iz = make_int4(0, 0, 0, 0);
    size_t stride = (size_t)gridDim.x * blockDim.x;
    for (size_t i = (size_t)blockIdx.x * blockDim.x + threadIdx.x; i < n_acc4; i += stride)
        acc4[i] = fz;
    for (size_t i = (size_t)blockIdx.x * blockDim.x + threadIdx.x; i < n_cnt4; i += stride)
        cnt4[i] = iz;
}

// ---------------------------------------------------------------------------
extern "C" void kernel_launch(void* const* d_in, const int* in_sizes, int n_in,
                              void* d_out, int out_size) {
    const float* xyz  = (const float*)d_in[0];   // (B, N, 3) float32
    const float* feat = (const float*)d_in[1];   // (B, C, N) float32
    float* out = (float*)d_out;                  // (B, 3, C, R, R) float32

    // Zero scratch via async memset nodes (driver path; cheaper than a
    // grid-stride kernel). cudaGetSymbolAddress is a host-side query — not a
    // stream op, capture-safe, no allocation. Called every time (stateless).
    void* acc_ptr = nullptr;
    void* cnt_ptr = nullptr;
    cudaError_t e1 = cudaGetSymbolAddress(&acc_ptr, g_acc);
    cudaError_t e2 = cudaGetSymbolAddress(&cnt_ptr, g_cnt);
    if (e1 == cudaSuccess && e2 == cudaSuccess && acc_ptr && cnt_ptr) {
        cudaMemsetAsync(acc_ptr, 0, sizeof(__half2) * (size_t)BB * NPLANES * R2 * (CC / 2));
        cudaMemsetAsync(cnt_ptr, 0, sizeof(int) * (size_t)BB * NPLANES * R2);
    } else {
        zero_scratch_kernel<<<2048, 256>>>();
    }

    int nthreads = BB * (NN / 4);                // 400000
    scatter_kernel<<<(nthreads + 255) / 256, 256>>>(xyz, feat);

    dim3 fg(R2 / 128, BB * NPLANES);
    finalize_kernel<<<fg, 256>>>(out);
}